// round 12
// baseline (speedup 1.0000x reference)
#include <cuda_runtime.h>
#include <cuda_fp16.h>
#include <cstdint>

// MotilityModel, fully tensor-core. R12: register-resident W1 B-fragments
// (warp tile 64rows x 32cols -> 32 regs of W1, zero per-tile B LDS),
// dedicated stat pass, A fp16 double-buffered + ldmatrix.
//   h = cs @ W1^T + b1 ; h = LN(h)*gamma+beta ; relu ; out = h @ W2^T + b2
// N=500000, CS=64, H=256, S=3, fp32 in/out.

#define N_CELLS 500000
#define TILE_M  64
#define T_TILES ((N_CELLS + TILE_M - 1) / TILE_M)   // 7813
#define THREADS 256                                  // 8 warps

#define ASTH 72   // A row stride in halfs (144B): ldmatrix conflict-free

// ---- smem layout (float offsets) ----
#define AH_OFF   0                       // A fp16 [2][64][ASTH]
#define AH_BUF_F (TILE_M * ASTH / 2)     // 2304 floats per buffer
#define AH_F     (2 * AH_BUF_F)
#define B1_OFF   (AH_OFF + AH_F)         // b1 [256]
#define PGB_OFF  (B1_OFF + 256)          // [128] float4 {g0,g1,be0,be1}
#define B2_OFF   (PGB_OFF + 512)
#define SR_OFF   (B2_OFF + 4)            // [64 rows][8 grp] float2 partials
#define STT_OFF  (SR_OFF + 1024)         // [64 rows] float2 stats
#define FR_OFF   (STT_OFF + 128)         // [64 rows][8 grp * 4] float
#define SMEM_F   (FR_OFF + 2048)         // 8580 floats = 34320 B

typedef unsigned long long ull;

__device__ __forceinline__ uint32_t h2(float lo, float hi) {
    __half2 h = __floats2half2_rn(lo, hi);
    return *reinterpret_cast<uint32_t*>(&h);
}

// ---- packed f32x2 helpers ----
__device__ __forceinline__ ull pk2(float lo, float hi) {
    ull r; asm("mov.b64 %0, {%1, %2};" : "=l"(r) : "f"(lo), "f"(hi)); return r;
}
__device__ __forceinline__ void upk2(ull p, float& lo, float& hi) {
    asm("mov.b64 {%0, %1}, %2;" : "=f"(lo), "=f"(hi) : "l"(p));
}
__device__ __forceinline__ ull f2fma(ull a, ull b, ull c) {
    ull d; asm("fma.rn.f32x2 %0, %1, %2, %3;" : "=l"(d) : "l"(a), "l"(b), "l"(c)); return d;
}
__device__ __forceinline__ ull f2add(ull a, ull b) {
    ull d; asm("add.rn.f32x2 %0, %1, %2;" : "=l"(d) : "l"(a), "l"(b)); return d;
}
__device__ __forceinline__ ull f2mul(ull a, ull b) {
    ull d; asm("mul.rn.f32x2 %0, %1, %2;" : "=l"(d) : "l"(a), "l"(b)); return d;
}

#define MMA_F16(c, a0, a1, a2, a3, bv0, bv1) \
    asm volatile("mma.sync.aligned.m16n8k16.row.col.f32.f16.f16.f32 " \
        "{%0,%1,%2,%3}, {%4,%5,%6,%7}, {%8,%9}, {%0,%1,%2,%3};" \
        : "+f"((c)[0]), "+f"((c)[1]), "+f"((c)[2]), "+f"((c)[3]) \
        : "r"(a0), "r"(a1), "r"(a2), "r"(a3), "r"(bv0), "r"(bv1))

#define LDMX4(r0, r1, r2, r3, addr) \
    asm volatile("ldmatrix.sync.aligned.m8n8.x4.shared.b16 {%0,%1,%2,%3}, [%4];" \
        : "=r"(r0), "=r"(r1), "=r"(r2), "=r"(r3) : "r"(addr))

struct TrueT  { static constexpr bool value = true;  };
struct FalseT { static constexpr bool value = false; };

__global__ void __launch_bounds__(THREADS, 2) motility_mma_kernel(
    const float* __restrict__ cs,   const float* __restrict__ W1,
    const float* __restrict__ b1,   const float* __restrict__ gamma,
    const float* __restrict__ beta, const float* __restrict__ W2,
    const float* __restrict__ b2,   float* __restrict__ out)
{
    extern __shared__ float sm[];
    float* b1s  = sm + B1_OFF;
    float* pgb  = sm + PGB_OFF;
    float* b2s  = sm + B2_OFF;
    float* sred = sm + SR_OFF;      // float2 [row][8]
    float* stt  = sm + STT_OFF;     // float2 [row]
    float* fred = sm + FR_OFF;      // float  [row][32]

    const int tid  = threadIdx.x;
    const int lane = tid & 31;
    const int warp = tid >> 5;          // 0..7; warp owns cols warp*32..+31
    const int g    = lane >> 2;         // 0..7
    const int tg   = lane & 3;          // 0..3
    const int bid  = blockIdx.x;
    const int GRID = gridDim.x;

    const uint32_t Au = (uint32_t)__cvta_generic_to_shared(sm + AH_OFF);
    const uint32_t lm_lane_off = (uint32_t)(lane & 15) * (ASTH * 2) + (uint32_t)(lane >> 4) * 16;

    // A staging role: row = tid>>2 (0..63), cq = (tid&3)*16
    const int st_row = tid >> 2;
    const int st_cq  = (tid & 3) * 16;
    const uint32_t st_dst = Au + (uint32_t)(st_row * ASTH + st_cq) * 2;

    const int nT = (T_TILES - 1 - bid) / GRID + 1;

    // ---- register-resident W1 B-fragments: b[kk][nt][2] (32 regs, once) ----
    uint32_t bfr[4][4][2];
    #pragma unroll
    for (int kk = 0; kk < 4; kk++)
        #pragma unroll
        for (int nt = 0; nt < 4; nt++) {
            const float* wr = W1 + (warp * 32 + nt * 8 + g) * 64 + kk * 16 + tg * 2;
            bfr[kk][nt][0] = h2(wr[0], wr[1]);
            bfr[kk][nt][1] = h2(wr[8], wr[9]);
        }

    // ---- W2 fp16 B-fragments for GEMM2 (2 q-chunks of k16) ----
    uint32_t w2f[2][2];
    #pragma unroll
    for (int q = 0; q < 2; q++) {
        if (g < 3) {
            const float* wr = W2 + g * 256 + warp * 32 + q * 16 + tg * 2;
            w2f[q][0] = h2(wr[0], wr[1]);
            w2f[q][1] = h2(wr[8], wr[9]);
        } else {
            w2f[q][0] = 0u; w2f[q][1] = 0u;
        }
    }

    // ---- params ----
    b1s[tid] = b1[tid];
    if (tid < 128) {
        int c0 = 2 * tid;
        reinterpret_cast<float4*>(pgb)[tid] =
            make_float4(gamma[c0], gamma[c0 + 1], beta[c0], beta[c0 + 1]);
    }
    if (tid < 3) b2s[tid] = b2[tid];

    float4 pf[4];
    auto ldgA = [&](int j) {
        long tile = (long)bid + (long)j * GRID;
        long cell = tile * TILE_M + st_row;
        if (j < nT && cell < N_CELLS) {
            const float4* src = reinterpret_cast<const float4*>(cs + cell * 64 + st_cq);
            pf[0] = src[0]; pf[1] = src[1]; pf[2] = src[2]; pf[3] = src[3];
        } else {
            pf[0] = pf[1] = pf[2] = pf[3] = make_float4(0, 0, 0, 0);
        }
    };
    auto stsA = [&](int buf) {
        uint4 lo, hi;
        lo.x = h2(pf[0].x, pf[0].y); lo.y = h2(pf[0].z, pf[0].w);
        lo.z = h2(pf[1].x, pf[1].y); lo.w = h2(pf[1].z, pf[1].w);
        hi.x = h2(pf[2].x, pf[2].y); hi.y = h2(pf[2].z, pf[2].w);
        hi.z = h2(pf[3].x, pf[3].y); hi.w = h2(pf[3].z, pf[3].w);
        uint32_t d0 = st_dst + (uint32_t)buf * (AH_BUF_F * 4);
        asm volatile("st.shared.v4.b32 [%0], {%1,%2,%3,%4};"
                     :: "r"(d0), "r"(lo.x), "r"(lo.y), "r"(lo.z), "r"(lo.w) : "memory");
        asm volatile("st.shared.v4.b32 [%0], {%1,%2,%3,%4};"
                     :: "r"(d0 + 16), "r"(hi.x), "r"(hi.y), "r"(hi.z), "r"(hi.w) : "memory");
    };

    ldgA(0);
    stsA(0);

    // ---- trivial-affine detection (also the staging barrier) ----
    int nontriv = (b1[tid] != 0.0f) | (gamma[tid] != 1.0f) | (beta[tid] != 0.0f);
    if (tid < 3) nontriv |= (b2[tid] != 0.0f);
    const bool trivial = (__syncthreads_or(nontriv) == 0);

    auto runloop = [&](auto trivc) {
        constexpr bool TRIV = decltype(trivc)::value;

        for (int j = 0; j < nT; j++) {
            const long tile = (long)bid + (long)j * GRID;

            // ---- acc init ----
            float acc[4][4][4];     // [mt 16-row][nt 8-col][4]
            if constexpr (TRIV) {
                #pragma unroll
                for (int mt = 0; mt < 4; mt++)
                    #pragma unroll
                    for (int nt = 0; nt < 4; nt++)
                        #pragma unroll
                        for (int qq = 0; qq < 4; qq++) acc[mt][nt][qq] = 0.0f;
            } else {
                #pragma unroll
                for (int nt = 0; nt < 4; nt++) {
                    int colp = warp * 16 + nt * 4 + tg;
                    float2 bv = reinterpret_cast<const float2*>(b1s)[colp];
                    #pragma unroll
                    for (int mt = 0; mt < 4; mt++) {
                        acc[mt][nt][0] = bv.x; acc[mt][nt][1] = bv.y;
                        acc[mt][nt][2] = bv.x; acc[mt][nt][3] = bv.y;
                    }
                }
            }

            // ---- GEMM1: 4 k16 steps; warp tile 64x32; B in registers ----
            const uint32_t Abase = Au + (uint32_t)((j & 1) * (AH_BUF_F * 4));
            #pragma unroll
            for (int kk = 0; kk < 4; kk++) {
                uint32_t a[4][4];
                #pragma unroll
                for (int mt = 0; mt < 4; mt++) {
                    uint32_t addr = Abase
                        + (uint32_t)(mt * 16 * (ASTH * 2) + kk * 32) + lm_lane_off;
                    LDMX4(a[mt][0], a[mt][1], a[mt][2], a[mt][3], addr);
                }
                #pragma unroll
                for (int mt = 0; mt < 4; mt++)
                    #pragma unroll
                    for (int nt = 0; nt < 4; nt++)
                        MMA_F16(acc[mt][nt],
                                a[mt][0], a[mt][1], a[mt][2], a[mt][3],
                                bfr[kk][nt][0], bfr[kk][nt][1]);
            }

            // ---- prefetch next A tile ----
            ldgA(j + 1);

            // ---- LN partials over this warp's 32 cols (packed f32x2) ----
            #pragma unroll
            for (int mt = 0; mt < 4; mt++) {
                ull s1p[2] = {0, 0}, s2p[2] = {0, 0};
                #pragma unroll
                for (int nt = 0; nt < 4; nt++)
                    #pragma unroll
                    for (int h = 0; h < 2; h++) {
                        ull v = pk2(acc[mt][nt][2 * h], acc[mt][nt][2 * h + 1]);
                        s1p[h] = f2add(s1p[h], v);
                        s2p[h] = f2fma(v, v, s2p[h]);
                    }
                #pragma unroll
                for (int h = 0; h < 2; h++) {
                    float lo, hi, s1, s2;
                    upk2(s1p[h], lo, hi); s1 = lo + hi;
                    upk2(s2p[h], lo, hi); s2 = lo + hi;
                    #pragma unroll
                    for (int o = 1; o <= 2; o <<= 1) {
                        s1 += __shfl_xor_sync(0xffffffffu, s1, o);
                        s2 += __shfl_xor_sync(0xffffffffu, s2, o);
                    }
                    if (tg == 0) {
                        int row = mt * 16 + g + 8 * h;
                        reinterpret_cast<float2*>(sred)[row * 8 + warp] =
                            make_float2(s1, s2);
                    }
                }
            }
            __syncthreads();    // SYNC1: sred visible

            // ---- stat pass: one thread per row ----
            if (tid < 64) {
                const float4* p = reinterpret_cast<const float4*>(sred) + tid * 4;
                float4 v0 = p[0], v1 = p[1], v2 = p[2], v3 = p[3];
                float t1 = (v0.x + v0.z) + (v1.x + v1.z) + (v2.x + v2.z) + (v3.x + v3.z);
                float t2 = (v0.y + v0.w) + (v1.y + v1.w) + (v2.y + v2.w) + (v3.y + v3.w);
                float m  = t1 * (1.0f / 256.0f);
                float var = fmaf(-m, m, t2 * (1.0f / 256.0f));
                float rs = rsqrtf(var + 1e-5f);
                if constexpr (TRIV)
                    reinterpret_cast<float2*>(stt)[tid] = make_float2(rs, -m * rs);
                else
                    reinterpret_cast<float2*>(stt)[tid] = make_float2(m, rs);
            }
            __syncthreads();    // SYNC1b: stats visible

            // ---- per-lane stats for its 8 rows ----
            ull rs_p[4][2], off_p[4][2];    // TRIV: off = -mu*rs ; else: off = -mu
            #pragma unroll
            for (int mt = 0; mt < 4; mt++)
                #pragma unroll
                for (int h = 0; h < 2; h++) {
                    int row = mt * 16 + g + 8 * h;
                    float2 sv = reinterpret_cast<const float2*>(stt)[row];
                    if constexpr (TRIV) {
                        rs_p[mt][h]  = pk2(sv.x, sv.x);
                        off_p[mt][h] = pk2(sv.y, sv.y);
                    } else {
                        rs_p[mt][h]  = pk2(sv.y, sv.y);
                        off_p[mt][h] = pk2(-sv.x, -sv.x);
                    }
                }

            // ---- normalize + relu -> fp16 frags -> GEMM2 MMA ----
            float d[4][4];
            #pragma unroll
            for (int mt = 0; mt < 4; mt++)
                #pragma unroll
                for (int qq = 0; qq < 4; qq++) d[mt][qq] = 0.0f;

            #pragma unroll
            for (int q = 0; q < 2; q++) {
                uint32_t hf[2][4][2];   // [p][mt][h]
                #pragma unroll
                for (int p = 0; p < 2; p++) {
                    int nt = 2 * q + p;
                    ull gv = 0, bev = 0;
                    if constexpr (!TRIV) {
                        int colp = warp * 16 + nt * 4 + tg;
                        float4 pv = reinterpret_cast<const float4*>(pgb)[colp];
                        gv  = pk2(pv.x, pv.y);
                        bev = pk2(pv.z, pv.w);
                    }
                    #pragma unroll
                    for (int mt = 0; mt < 4; mt++)
                        #pragma unroll
                        for (int h = 0; h < 2; h++) {
                            ull ap = pk2(acc[mt][nt][2*h], acc[mt][nt][2*h+1]);
                            ull vp;
                            if constexpr (TRIV) {
                                vp = f2fma(ap, rs_p[mt][h], off_p[mt][h]);
                            } else {
                                ull A = f2mul(rs_p[mt][h], gv);
                                ull B = f2fma(off_p[mt][h], A, bev);
                                vp = f2fma(ap, A, B);
                            }
                            float v0, v1;
                            upk2(vp, v0, v1);
                            v0 = fmaxf(v0, 0.0f); v1 = fmaxf(v1, 0.0f);
                            hf[p][mt][h] = h2(v0, v1);
                        }
                }
                #pragma unroll
                for (int mt = 0; mt < 4; mt++)
                    MMA_F16(d[mt],
                            hf[0][mt][0], hf[0][mt][1], hf[1][mt][0], hf[1][mt][1],
                            w2f[q][0], w2f[q][1]);
            }

            // ---- store per-warp partial forces ----
            if (tg < 2) {
                #pragma unroll
                for (int mt = 0; mt < 4; mt++) {
                    int row0 = mt * 16 + g;
                    if (tg == 0) {
                        fred[row0 * 32 + warp * 4 + 0] = d[mt][0];
                        fred[row0 * 32 + warp * 4 + 1] = d[mt][1];
                        fred[(row0 + 8) * 32 + warp * 4 + 0] = d[mt][2];
                        fred[(row0 + 8) * 32 + warp * 4 + 1] = d[mt][3];
                    } else {
                        fred[row0 * 32 + warp * 4 + 2] = d[mt][0];
                        fred[(row0 + 8) * 32 + warp * 4 + 2] = d[mt][2];
                    }
                }
            }
            stsA((j + 1) & 1);  // next A buffer (its readers finished last tile)
            __syncthreads();    // SYNC2: fred + A(j+1) visible

            if (tid < 192) {
                int row = tid / 3, s = tid - row * 3;
                long cell = tile * TILE_M + row;
                if (cell < N_CELLS) {
                    const float* fr = fred + row * 32 + s;
                    float v = fr[0] + fr[4] + fr[8] + fr[12]
                            + fr[16] + fr[20] + fr[24] + fr[28];
                    if constexpr (!TRIV) v += b2s[s];
                    out[tile * (TILE_M * 3) + tid] = v;
                }
            }
            // next tile's smem writes ordered behind SYNC1/SYNC1b/SYNC2
        }
    };

    if (trivial) runloop(TrueT{});
    else         runloop(FalseT{});
}

extern "C" void kernel_launch(void* const* d_in, const int* in_sizes, int n_in,
                              void* d_out, int out_size)
{
    const float* cs    = (const float*)d_in[0];
    const float* W1    = (const float*)d_in[1];
    const float* b1    = (const float*)d_in[2];
    const float* gamma = (const float*)d_in[3];
    const float* beta  = (const float*)d_in[4];
    const float* W2    = (const float*)d_in[5];
    const float* b2    = (const float*)d_in[6];
    float* out = (float*)d_out;

    int dev = 0, sms = 148;
    cudaGetDevice(&dev);
    cudaDeviceGetAttribute(&sms, cudaDevAttrMultiProcessorCount, dev);
    if (sms <= 0) sms = 148;
    int grid = 2 * sms;
    if (grid > T_TILES) grid = T_TILES;

    const size_t smem = SMEM_F * sizeof(float);   // 34320 B
    cudaFuncSetAttribute(motility_mma_kernel,
                         cudaFuncAttributeMaxDynamicSharedMemorySize, (int)smem);
    motility_mma_kernel<<<grid, THREADS, smem>>>(cs, W1, b1, gamma, beta, W2, b2, out);
}

// round 13
// speedup vs baseline: 1.7011x; 1.7011x over previous
#include <cuda_runtime.h>
#include <cuda_fp16.h>
#include <cstdint>

// MotilityModel, fully tensor-core (R11 base). R13: the two row-halves of
// each CTA run on independent NAMED barriers (4 barrier domains/SM without
// duplicating W1 smem) + relu fused into fp16 cvt.
//   h = cs @ W1^T + b1 ; h = LN(h)*gamma+beta ; relu ; out = h @ W2^T + b2
// N=500000, CS=64, H=256, S=3, fp32 in/out.

#define N_CELLS 500000
#define TILE_M  64
#define T_TILES ((N_CELLS + TILE_M - 1) / TILE_M)   // 7813
#define THREADS 256                                  // 8 warps

#define ASTH 72   // A row stride in halfs (144B): ldmatrix conflict-free

// ---- smem layout (float offsets) ----
#define W1F_OFF 0
#define W1F_F   8192                     // 32KB fp16 B fragment-major
#define AH_OFF  (W1F_OFF + W1F_F)        // A fp16 [2][64][ASTH] halfs
#define AH_BUF_F (TILE_M * ASTH / 2)     // 2304 floats per buffer
#define AH_F    (2 * AH_BUF_F)
#define B1_OFF  (AH_OFF + AH_F)          // b1 [256]
#define PGB_OFF (B1_OFF + 256)           // [128 colp] float4 {g0,g1,be0,be1}
#define B2_OFF  (PGB_OFF + 512)
#define SR_OFF  (B2_OFF + 4)             // [4 ng][64 rows] float2 (s1,s2)
#define FR_OFF  (SR_OFF + 512)           // [4 ng][64 rows][4] float
#define SMEM_F  (FR_OFF + 1024)          // 15108 floats = 60432 B

typedef unsigned long long ull;

__device__ __forceinline__ uint32_t h2(float lo, float hi) {
    __half2 h = __floats2half2_rn(lo, hi);
    return *reinterpret_cast<uint32_t*>(&h);
}

// ---- packed f32x2 helpers ----
__device__ __forceinline__ ull pk2(float lo, float hi) {
    ull r; asm("mov.b64 %0, {%1, %2};" : "=l"(r) : "f"(lo), "f"(hi)); return r;
}
__device__ __forceinline__ void upk2(ull p, float& lo, float& hi) {
    asm("mov.b64 {%0, %1}, %2;" : "=f"(lo), "=f"(hi) : "l"(p));
}
__device__ __forceinline__ ull f2fma(ull a, ull b, ull c) {
    ull d; asm("fma.rn.f32x2 %0, %1, %2, %3;" : "=l"(d) : "l"(a), "l"(b), "l"(c)); return d;
}
__device__ __forceinline__ ull f2add(ull a, ull b) {
    ull d; asm("add.rn.f32x2 %0, %1, %2;" : "=l"(d) : "l"(a), "l"(b)); return d;
}
__device__ __forceinline__ ull f2mul(ull a, ull b) {
    ull d; asm("mul.rn.f32x2 %0, %1, %2;" : "=l"(d) : "l"(a), "l"(b)); return d;
}
// relu fused into fp16x2 convert: identical result to fmax(0)+cvt
__device__ __forceinline__ uint32_t h2relu(ull vp) {
    float lo, hi; upk2(vp, lo, hi);
    uint32_t r;
    asm("cvt.rn.relu.f16x2.f32 %0, %1, %2;" : "=r"(r) : "f"(hi), "f"(lo));
    return r;
}

#define MMA_F16(c, a0, a1, a2, a3, bv0, bv1) \
    asm volatile("mma.sync.aligned.m16n8k16.row.col.f32.f16.f16.f32 " \
        "{%0,%1,%2,%3}, {%4,%5,%6,%7}, {%8,%9}, {%0,%1,%2,%3};" \
        : "+f"((c)[0]), "+f"((c)[1]), "+f"((c)[2]), "+f"((c)[3]) \
        : "r"(a0), "r"(a1), "r"(a2), "r"(a3), "r"(bv0), "r"(bv1))

#define LDMX4(r0, r1, r2, r3, addr) \
    asm volatile("ldmatrix.sync.aligned.m8n8.x4.shared.b16 {%0,%1,%2,%3}, [%4];" \
        : "=r"(r0), "=r"(r1), "=r"(r2), "=r"(r3) : "r"(addr))

struct TrueT  { static constexpr bool value = true;  };
struct FalseT { static constexpr bool value = false; };

__global__ void __launch_bounds__(THREADS, 2) motility_mma_kernel(
    const float* __restrict__ cs,   const float* __restrict__ W1,
    const float* __restrict__ b1,   const float* __restrict__ gamma,
    const float* __restrict__ beta, const float* __restrict__ W2,
    const float* __restrict__ b2,   float* __restrict__ out)
{
    extern __shared__ float sm[];
    float* W1f  = sm + W1F_OFF;
    float* b1s  = sm + B1_OFF;
    float* pgb  = sm + PGB_OFF;
    float* b2s  = sm + B2_OFF;
    float* sred = sm + SR_OFF;
    float* fred = sm + FR_OFF;

    const int tid  = threadIdx.x;
    const int lane = tid & 31;
    const int warp = tid >> 5;          // 0..7
    const int g    = lane >> 2;         // 0..7
    const int tg   = lane & 3;          // 0..3
    const int half    = warp & 1;       // owns rows half*32..+31 (indep. barrier)
    const int n_group = warp >> 1;      // cols n_group*64..+63
    const int hwtid   = n_group * 32 + lane;   // 0..127 within half
    const int bid  = blockIdx.x;
    const int GRID = gridDim.x;

    // per-half named barrier (ids 1 and 2; 128 threads each)
    const int barid = 1 + half;
    #define BARH() asm volatile("bar.sync %0, 128;" :: "r"(barid) : "memory")

    const uint32_t Au = (uint32_t)__cvta_generic_to_shared(sm + AH_OFF);
    const uint32_t lm_lane_off = (uint32_t)(lane & 15) * (ASTH * 2) + (uint32_t)(lane >> 4) * 16;

    // A staging role (per half): row = half*32 + hwtid>>2, cq = (hwtid&3)*16
    const int st_row = half * 32 + (hwtid >> 2);
    const int st_cq  = (hwtid & 3) * 16;
    const uint32_t st_dst = Au + (uint32_t)(st_row * ASTH + st_cq) * 2;

    const int nT = (T_TILES - 1 - bid) / GRID + 1;

    // ---- W2 fp16 B-fragments for GEMM2 (per-warp registers, once) ----
    uint32_t w2f[4][2];
    #pragma unroll
    for (int q = 0; q < 4; q++) {
        if (g < 3) {
            const float* wr = W2 + g * 256 + n_group * 64 + q * 16 + tg * 2;
            w2f[q][0] = h2(wr[0], wr[1]);
            w2f[q][1] = h2(wr[8], wr[9]);
        } else {
            w2f[q][0] = 0u; w2f[q][1] = 0u;
        }
    }

    // ---- stage W1 as fp16 fragments (once) ----
    #pragma unroll
    for (int i = 0; i < 8; i++) {
        int idx = tid + i * THREADS;            // 0..2047
        int li  = idx & 31;
        int rg  = (idx >> 5) & 3;
        int ng  = (idx >> 7) & 3;
        int kk  = idx >> 9;
        int gg = li >> 2, tt = li & 3;
        int k0 = kk * 16 + tt * 2;
        int ca = ng * 64 + (rg * 2) * 8 + gg;
        int cb = ca + 8;
        uint4 v;
        v.x = h2(W1[ca * 64 + k0],     W1[ca * 64 + k0 + 1]);
        v.y = h2(W1[ca * 64 + k0 + 8], W1[ca * 64 + k0 + 9]);
        v.z = h2(W1[cb * 64 + k0],     W1[cb * 64 + k0 + 1]);
        v.w = h2(W1[cb * 64 + k0 + 8], W1[cb * 64 + k0 + 9]);
        reinterpret_cast<uint4*>(W1f)[idx] = v;
    }
    b1s[tid] = b1[tid];
    if (tid < 128) {
        int c0 = 2 * tid;
        reinterpret_cast<float4*>(pgb)[tid] =
            make_float4(gamma[c0], gamma[c0 + 1], beta[c0], beta[c0 + 1]);
    }
    if (tid < 3) b2s[tid] = b2[tid];

    float4 pf[4];
    auto ldgA = [&](int j) {
        long tile = (long)bid + (long)j * GRID;
        long cell = tile * TILE_M + st_row;
        if (j < nT && cell < N_CELLS) {
            const float4* src = reinterpret_cast<const float4*>(cs + cell * 64 + st_cq);
            pf[0] = src[0]; pf[1] = src[1]; pf[2] = src[2]; pf[3] = src[3];
        } else {
            pf[0] = pf[1] = pf[2] = pf[3] = make_float4(0, 0, 0, 0);
        }
    };
    auto stsA = [&](int buf) {
        uint4 lo, hi;
        lo.x = h2(pf[0].x, pf[0].y); lo.y = h2(pf[0].z, pf[0].w);
        lo.z = h2(pf[1].x, pf[1].y); lo.w = h2(pf[1].z, pf[1].w);
        hi.x = h2(pf[2].x, pf[2].y); hi.y = h2(pf[2].z, pf[2].w);
        hi.z = h2(pf[3].x, pf[3].y); hi.w = h2(pf[3].z, pf[3].w);
        uint32_t d0 = st_dst + (uint32_t)buf * (AH_BUF_F * 4);
        asm volatile("st.shared.v4.b32 [%0], {%1,%2,%3,%4};"
                     :: "r"(d0), "r"(lo.x), "r"(lo.y), "r"(lo.z), "r"(lo.w) : "memory");
        asm volatile("st.shared.v4.b32 [%0], {%1,%2,%3,%4};"
                     :: "r"(d0 + 16), "r"(hi.x), "r"(hi.y), "r"(hi.z), "r"(hi.w) : "memory");
    };

    ldgA(0);
    stsA(0);

    // ---- trivial-affine detection (full-CTA barrier; also covers staging) ----
    int nontriv = (b1[tid] != 0.0f) | (gamma[tid] != 1.0f) | (beta[tid] != 0.0f);
    if (tid < 3) nontriv |= (b2[tid] != 0.0f);
    const bool trivial = (__syncthreads_or(nontriv) == 0);

    const uint4* Bf = reinterpret_cast<const uint4*>(W1f) + n_group * 128 + lane;

    auto runloop = [&](auto trivc) {
        constexpr bool TRIV = decltype(trivc)::value;

        for (int j = 0; j < nT; j++) {
            const long tile = (long)bid + (long)j * GRID;

            // ---- acc init ----
            float acc[2][8][4];
            if constexpr (TRIV) {
                #pragma unroll
                for (int nt = 0; nt < 8; nt++)
                    #pragma unroll
                    for (int mt = 0; mt < 2; mt++)
                        #pragma unroll
                        for (int qq = 0; qq < 4; qq++) acc[mt][nt][qq] = 0.0f;
            } else {
                #pragma unroll
                for (int nt = 0; nt < 8; nt++) {
                    int colp = n_group * 32 + nt * 4 + tg;
                    float2 bv = reinterpret_cast<const float2*>(b1s)[colp];
                    #pragma unroll
                    for (int mt = 0; mt < 2; mt++) {
                        acc[mt][nt][0] = bv.x; acc[mt][nt][1] = bv.y;
                        acc[mt][nt][2] = bv.x; acc[mt][nt][3] = bv.y;
                    }
                }
            }

            // ---- GEMM1: rows half*32..+31, cols n_group*64..+63 ----
            const uint32_t Abase = Au + (uint32_t)((j & 1) * (AH_BUF_F * 4));
            #pragma unroll
            for (int kk = 0; kk < 4; kk++) {
                uint4 bb[4];
                #pragma unroll
                for (int rg = 0; rg < 4; rg++)
                    bb[rg] = Bf[kk * 512 + rg * 32];

                uint32_t a[2][4];
                #pragma unroll
                for (int mt = 0; mt < 2; mt++) {
                    uint32_t addr = Abase
                        + (uint32_t)((half * 32 + mt * 16) * (ASTH * 2) + kk * 32)
                        + lm_lane_off;
                    LDMX4(a[mt][0], a[mt][1], a[mt][2], a[mt][3], addr);
                }
                #pragma unroll
                for (int mt = 0; mt < 2; mt++)
                    #pragma unroll
                    for (int rg = 0; rg < 4; rg++) {
                        MMA_F16(acc[mt][2 * rg],
                                a[mt][0], a[mt][1], a[mt][2], a[mt][3],
                                bb[rg].x, bb[rg].y);
                        MMA_F16(acc[mt][2 * rg + 1],
                                a[mt][0], a[mt][1], a[mt][2], a[mt][3],
                                bb[rg].z, bb[rg].w);
                    }
            }

            // ---- prefetch next A tile (own half's rows) ----
            ldgA(j + 1);

            // ---- LN statistics (packed f32x2) ----
            ull s1p[2][2], s2p[2][2];
            #pragma unroll
            for (int mt = 0; mt < 2; mt++)
                #pragma unroll
                for (int h = 0; h < 2; h++) { s1p[mt][h] = 0ull; s2p[mt][h] = 0ull; }
            #pragma unroll
            for (int nt = 0; nt < 8; nt++)
                #pragma unroll
                for (int mt = 0; mt < 2; mt++)
                    #pragma unroll
                    for (int h = 0; h < 2; h++) {
                        ull v = pk2(acc[mt][nt][2 * h], acc[mt][nt][2 * h + 1]);
                        s1p[mt][h] = f2add(s1p[mt][h], v);
                        s2p[mt][h] = f2fma(v, v, s2p[mt][h]);
                    }
            float s1[2][2], s2[2][2];
            #pragma unroll
            for (int mt = 0; mt < 2; mt++)
                #pragma unroll
                for (int h = 0; h < 2; h++) {
                    float lo, hi;
                    upk2(s1p[mt][h], lo, hi); s1[mt][h] = lo + hi;
                    upk2(s2p[mt][h], lo, hi); s2[mt][h] = lo + hi;
                }
            #pragma unroll
            for (int o = 1; o <= 2; o <<= 1)
                #pragma unroll
                for (int mt = 0; mt < 2; mt++)
                    #pragma unroll
                    for (int h = 0; h < 2; h++) {
                        s1[mt][h] += __shfl_xor_sync(0xffffffffu, s1[mt][h], o);
                        s2[mt][h] += __shfl_xor_sync(0xffffffffu, s2[mt][h], o);
                    }
            if (tg == 0) {
                #pragma unroll
                for (int mt = 0; mt < 2; mt++)
                    #pragma unroll
                    for (int h = 0; h < 2; h++) {
                        int row = half * 32 + mt * 16 + g + 8 * h;
                        reinterpret_cast<float2*>(sred)[n_group * 64 + row] =
                            make_float2(s1[mt][h], s2[mt][h]);
                    }
            }
            BARH();             // SYNC1 (per half): sred rows of this half visible

            ull rs_p[2][2], off_p[2][2];
            #pragma unroll
            for (int mt = 0; mt < 2; mt++)
                #pragma unroll
                for (int h = 0; h < 2; h++) {
                    int row = half * 32 + mt * 16 + g + 8 * h;
                    float t1 = 0.f, t2 = 0.f;
                    #pragma unroll
                    for (int ng = 0; ng < 4; ng++) {
                        float2 v = reinterpret_cast<const float2*>(sred)[ng * 64 + row];
                        t1 += v.x; t2 += v.y;
                    }
                    float m = t1 * (1.0f / 256.0f);
                    float var = fmaf(-m, m, t2 * (1.0f / 256.0f));
                    float rs = rsqrtf(var + 1e-5f);
                    rs_p[mt][h] = pk2(rs, rs);
                    if constexpr (TRIV) {
                        float nr = -m * rs;
                        off_p[mt][h] = pk2(nr, nr);
                    } else {
                        off_p[mt][h] = pk2(-m, -m);
                    }
                }

            // ---- normalize + relu(cvt-fused) -> fp16 frags -> GEMM2 MMA ----
            float d[2][4] = {{0, 0, 0, 0}, {0, 0, 0, 0}};
            #pragma unroll
            for (int q = 0; q < 4; q++) {
                uint32_t hf[2][2][2];
                #pragma unroll
                for (int p = 0; p < 2; p++) {
                    int nt = 2 * q + p;
                    ull gv = 0, bev = 0;
                    if constexpr (!TRIV) {
                        int colp = n_group * 32 + nt * 4 + tg;
                        float4 pv = reinterpret_cast<const float4*>(pgb)[colp];
                        gv  = pk2(pv.x, pv.y);
                        bev = pk2(pv.z, pv.w);
                    }
                    #pragma unroll
                    for (int mt = 0; mt < 2; mt++)
                        #pragma unroll
                        for (int h = 0; h < 2; h++) {
                            ull ap = pk2(acc[mt][nt][2*h], acc[mt][nt][2*h+1]);
                            ull vp;
                            if constexpr (TRIV) {
                                vp = f2fma(ap, rs_p[mt][h], off_p[mt][h]);
                            } else {
                                ull A = f2mul(rs_p[mt][h], gv);
                                ull B = f2fma(off_p[mt][h], A, bev);
                                vp = f2fma(ap, A, B);
                            }
                            hf[p][mt][h] = h2relu(vp);
                        }
                }
                #pragma unroll
                for (int mt = 0; mt < 2; mt++)
                    MMA_F16(d[mt],
                            hf[0][mt][0], hf[0][mt][1], hf[1][mt][0], hf[1][mt][1],
                            w2f[q][0], w2f[q][1]);
            }

            // ---- store per-n_group partial forces (rows of this half) ----
            if (tg < 2) {
                #pragma unroll
                for (int mt = 0; mt < 2; mt++) {
                    int row0 = half * 32 + mt * 16 + g;
                    float* fr = fred + n_group * 256;
                    if (tg == 0) {
                        fr[row0 * 4 + 0] = d[mt][0];
                        fr[row0 * 4 + 1] = d[mt][1];
                        fr[(row0 + 8) * 4 + 0] = d[mt][2];
                        fr[(row0 + 8) * 4 + 1] = d[mt][3];
                    } else {
                        fr[row0 * 4 + 2] = d[mt][0];
                        fr[(row0 + 8) * 4 + 2] = d[mt][2];
                    }
                }
            }
            stsA((j + 1) & 1);  // write next A buffer (own half's rows)
            BARH();             // SYNC2 (per half): fred + A(j+1) rows visible

            if (hwtid < 96) {
                int row = half * 32 + hwtid / 3;
                int s   = hwtid - (hwtid / 3) * 3;
                long cell = tile * TILE_M + row;
                if (cell < N_CELLS) {
                    float v = fred[row * 4 + s] + fred[256 + row * 4 + s]
                            + fred[512 + row * 4 + s] + fred[768 + row * 4 + s];
                    if constexpr (!TRIV) v += b2s[s];
                    out[tile * (TILE_M * 3) + row * 3 + s] = v;
                }
            }
            // next tile's smem writes for this half ordered behind its barriers
        }
    };

    if (trivial) runloop(TrueT{});
    else         runloop(FalseT{});
    #undef BARH
}

extern "C" void kernel_launch(void* const* d_in, const int* in_sizes, int n_in,
                              void* d_out, int out_size)
{
    const float* cs    = (const float*)d_in[0];
    const float* W1    = (const float*)d_in[1];
    const float* b1    = (const float*)d_in[2];
    const float* gamma = (const float*)d_in[3];
    const float* beta  = (const float*)d_in[4];
    const float* W2    = (const float*)d_in[5];
    const float* b2    = (const float*)d_in[6];
    float* out = (float*)d_out;

    int dev = 0, sms = 148;
    cudaGetDevice(&dev);
    cudaDeviceGetAttribute(&sms, cudaDevAttrMultiProcessorCount, dev);
    if (sms <= 0) sms = 148;
    int grid = 2 * sms;
    if (grid > T_TILES) grid = T_TILES;

    const size_t smem = SMEM_F * sizeof(float);   // 60432 B
    cudaFuncSetAttribute(motility_mma_kernel,
                         cudaFuncAttributeMaxDynamicSharedMemorySize, (int)smem);
    motility_mma_kernel<<<grid, THREADS, smem>>>(cs, W1, b1, gamma, beta, W2, b2, out);
}